// round 3
// baseline (speedup 1.0000x reference)
#include <cuda_runtime.h>

#define NF     65536
#define KIN    512
#define MH     128          // half of 2*N_MEMORY
#define TSCAN  65535
#define CHUNK  256
#define NCH    256          // CHUNK*NCH = 65536 >= TSCAN

// Scratch (device globals; no runtime allocation allowed)
__device__ __align__(16) float2 g_ab[(size_t)NF * MH];   // [f][j] -> (a, b)   64 MiB
__device__ float2 g_comp [NCH * MH];                     // per-chunk composite (A,B)
__device__ float  g_carry[NCH * MH];                     // state entering each chunk
__device__ __align__(16) float g_z[(size_t)NF * MH];     // [f][j]             32 MiB

// ---------------------------------------------------------------------------
// GEMM1: h = sigmoid(W1 @ inputs + B1); epilogue emits (a, b) interleaved,
// frame-major: g_ab[f*128 + j] = (h[j,f]*h[j+128,f], 1 - h[j,f])
// Tile: 256(M) x 64(N) per CTA, 256 threads, 8x8 per thread, K staged 16 wide.
// ---------------------------------------------------------------------------
__global__ __launch_bounds__(256, 2)
void k_gemm1(const float* __restrict__ inp, const float* __restrict__ W1,
             const float* __restrict__ B1)
{
    __shared__ float smem[9216];                          // 36 KB
    float (*sW)[256] = (float(*)[256])smem;               // [16][256]
    float (*sX)[72]  = (float(*)[72])(smem + 4096);       // [16][72]
    float (*sHL)[72] = (float(*)[72])smem;                // [128][72] overlay (post-loop)

    const int tx = threadIdx.x;
    const int trow = tx >> 3, tcol = tx & 7;
    const int m_base = trow * 8, f_base = tcol * 8;
    const int f0 = blockIdx.x * 64;

    float acc[8][8];
    #pragma unroll
    for (int i = 0; i < 8; i++)
        #pragma unroll
        for (int j = 0; j < 8; j++) acc[i][j] = 0.f;

    for (int k0 = 0; k0 < KIN; k0 += 16) {
        __syncthreads();
        {   // W1 tile: thread tx loads row m=tx, 16 contiguous k (float4 x4)
            const float4* wr = (const float4*)(W1 + (size_t)tx * KIN + k0);
            #pragma unroll
            for (int q = 0; q < 4; q++) {
                float4 v = wr[q];
                sW[4*q+0][tx] = v.x; sW[4*q+1][tx] = v.y;
                sW[4*q+2][tx] = v.z; sW[4*q+3][tx] = v.w;
            }
        }
        {   // input tile 16(k) x 64(f): coalesced along f
            int ff = tx & 63, kr = tx >> 6;
            #pragma unroll
            for (int r = 0; r < 4; r++) {
                int kk = kr + 4*r;
                sX[kk][ff] = inp[(size_t)(k0 + kk) * NF + f0 + ff];
            }
        }
        __syncthreads();
        #pragma unroll
        for (int kk = 0; kk < 16; kk++) {
            float4 wa = *(const float4*)&sW[kk][m_base];
            float4 wb = *(const float4*)&sW[kk][m_base + 4];
            float4 xa = *(const float4*)&sX[kk][f_base];
            float4 xb = *(const float4*)&sX[kk][f_base + 4];
            float wf[8] = {wa.x, wa.y, wa.z, wa.w, wb.x, wb.y, wb.z, wb.w};
            float xf[8] = {xa.x, xa.y, xa.z, xa.w, xb.x, xb.y, xb.z, xb.w};
            #pragma unroll
            for (int i = 0; i < 8; i++)
                #pragma unroll
                for (int j = 0; j < 8; j++)
                    acc[i][j] = fmaf(wf[i], xf[j], acc[i][j]);
        }
    }

    // sigmoid(acc + bias) in place
    #pragma unroll
    for (int i = 0; i < 8; i++) {
        float bias = __ldg(B1 + m_base + i);
        #pragma unroll
        for (int j = 0; j < 8; j++)
            acc[i][j] = 1.f / (1.f + __expf(-(acc[i][j] + bias)));
    }

    __syncthreads();                       // tiles dead; overlay sHL
    if (trow < 16) {                       // left half -> smem
        #pragma unroll
        for (int i = 0; i < 8; i++)
            #pragma unroll
            for (int j = 0; j < 8; j++)
                sHL[m_base + i][f_base + j] = acc[i][j];
    }
    __syncthreads();
    if (trow >= 16) {                      // right half: gate + emit (a,b)
        const int jb = m_base - 128;       // lane base, multiple of 8
        #pragma unroll
        for (int jj = 0; jj < 8; jj++) {
            float4 vv[4];
            #pragma unroll
            for (int q = 0; q < 4; q++) {
                float l0 = sHL[jb + 2*q    ][f_base + jj];
                float l1 = sHL[jb + 2*q + 1][f_base + jj];
                vv[q] = make_float4(l0 * acc[2*q  ][jj], 1.f - l0,
                                    l1 * acc[2*q+1][jj], 1.f - l1);
            }
            float4* p = (float4*)&g_ab[(size_t)(f0 + f_base + jj) * MH + jb];
            #pragma unroll
            for (int q = 0; q < 4; q++) p[q] = vv[q];
        }
    }
}

// ---------------------------------------------------------------------------
// Scan pass 1: per-chunk composite. State map: s' = A*s + B.
// Element update: s' = a*s + b  =>  A *= a, B = a*B + b.
// ---------------------------------------------------------------------------
__global__ __launch_bounds__(128)
void k_scan_chunks()
{
    const int c = blockIdx.x, j = threadIdx.x;
    const int t0 = c * CHUNK;
    const int n = min(CHUNK, TSCAN - t0);
    const float2* p = g_ab + (size_t)t0 * MH + j;
    float A = 1.f, B = 0.f;
    #pragma unroll 8
    for (int t = 0; t < n; t++) {
        float2 v = p[(size_t)t * MH];      // coalesced: 128 lanes contiguous
        B = fmaf(v.x, B, v.y);
        A *= v.x;
    }
    g_comp[c * MH + j] = make_float2(A, B);
}

// Scan pass 2: serial carry across NCH chunks (tiny).
__global__ void k_scan_carry()
{
    const int j = threadIdx.x;
    float s = 0.f;
    #pragma unroll 8
    for (int c = 0; c < NCH; c++) {
        g_carry[c * MH + j] = s;
        float2 v = g_comp[c * MH + j];
        s = fmaf(v.x, s, v.y);
    }
}

// Scan pass 3: apply carries, write z (frame-major). z[:,0] = 0; z[:,t]=s_{t-1}.
__global__ __launch_bounds__(128)
void k_scan_apply()
{
    const int c = blockIdx.x, j = threadIdx.x;
    const int t0 = c * CHUNK;
    const int n = min(CHUNK, TSCAN - t0);
    float s = g_carry[c * MH + j];
    if (c == 0) g_z[j] = 0.f;
    const float2* p  = g_ab + (size_t)t0 * MH + j;
    float*        zp = g_z  + (size_t)(t0 + 1) * MH + j;
    #pragma unroll 4
    for (int t = 0; t < n; t++) {
        float2 v = p[(size_t)t * MH];
        s = fmaf(v.x, s, v.y);
        zp[(size_t)t * MH] = s;            // coalesced
    }
}

// ---------------------------------------------------------------------------
// GEMM2: out = 1 - sigmoid(W2 @ z + B2) = sigmoid(-(W2 z + B2))
// Same tiling as GEMM1, K = 128. z read frame-major.
// ---------------------------------------------------------------------------
__global__ __launch_bounds__(256, 2)
void k_gemm2(const float* __restrict__ W2, const float* __restrict__ B2,
             float* __restrict__ out)
{
    __shared__ float sW[16][256];
    __shared__ float sZ[16][72];

    const int tx = threadIdx.x;
    const int trow = tx >> 3, tcol = tx & 7;
    const int m_base = trow * 8, f_base = tcol * 8;
    const int f0 = blockIdx.x * 64;

    float acc[8][8];
    #pragma unroll
    for (int i = 0; i < 8; i++)
        #pragma unroll
        for (int j = 0; j < 8; j++) acc[i][j] = 0.f;

    for (int k0 = 0; k0 < MH; k0 += 16) {
        __syncthreads();
        {
            const float4* wr = (const float4*)(W2 + (size_t)tx * MH + k0);
            #pragma unroll
            for (int q = 0; q < 4; q++) {
                float4 v = wr[q];
                sW[4*q+0][tx] = v.x; sW[4*q+1][tx] = v.y;
                sW[4*q+2][tx] = v.z; sW[4*q+3][tx] = v.w;
            }
        }
        {
            int jj = tx & 15, fr = tx >> 4;
            #pragma unroll
            for (int r = 0; r < 4; r++) {
                int ff = fr + 16*r;
                sZ[jj][ff] = g_z[(size_t)(f0 + ff) * MH + k0 + jj];
            }
        }
        __syncthreads();
        #pragma unroll
        for (int kk = 0; kk < 16; kk++) {
            float4 wa = *(const float4*)&sW[kk][m_base];
            float4 wb = *(const float4*)&sW[kk][m_base + 4];
            float4 xa = *(const float4*)&sZ[kk][f_base];
            float4 xb = *(const float4*)&sZ[kk][f_base + 4];
            float wf[8] = {wa.x, wa.y, wa.z, wa.w, wb.x, wb.y, wb.z, wb.w};
            float xf[8] = {xa.x, xa.y, xa.z, xa.w, xb.x, xb.y, xb.z, xb.w};
            #pragma unroll
            for (int i = 0; i < 8; i++)
                #pragma unroll
                for (int j = 0; j < 8; j++)
                    acc[i][j] = fmaf(wf[i], xf[j], acc[i][j]);
        }
    }

    #pragma unroll
    for (int i = 0; i < 8; i++) {
        float bias = __ldg(B2 + m_base + i);
        float o[8];
        #pragma unroll
        for (int j = 0; j < 8; j++)
            o[j] = 1.f / (1.f + __expf(acc[i][j] + bias));   // 1 - sigmoid(x)
        float* op = out + (size_t)(m_base + i) * NF + f0 + f_base;
        ((float4*)op)[0] = make_float4(o[0], o[1], o[2], o[3]);
        ((float4*)op)[1] = make_float4(o[4], o[5], o[6], o[7]);
    }
}

// ---------------------------------------------------------------------------
extern "C" void kernel_launch(void* const* d_in, const int* in_sizes, int n_in,
                              void* d_out, int out_size)
{
    const float* inp = (const float*)d_in[0];   // (512, 65536)
    const float* W1  = (const float*)d_in[1];   // (256, 512)
    const float* B1  = (const float*)d_in[2];   // (256, 1)
    const float* W2  = (const float*)d_in[3];   // (256, 128)
    const float* B2  = (const float*)d_in[4];   // (256, 1)
    float* out = (float*)d_out;                 // (256, 65536)

    k_gemm1<<<NF / 64, 256>>>(inp, W1, B1);
    k_scan_chunks<<<NCH, 128>>>();
    k_scan_carry<<<1, 128>>>();
    k_scan_apply<<<NCH, 128>>>();
    k_gemm2<<<NF / 64, 256>>>(W2, B2, out);
}

// round 7
// speedup vs baseline: 2.3910x; 2.3910x over previous
#include <cuda_runtime.h>
#include <cuda_fp16.h>
#include <cstdint>

#define NF     65536
#define TSCAN  65535
#define CHUNK  64
#define NCH    1024

// ===========================================================================
// Device scratch (no runtime allocation allowed)
// ===========================================================================
__device__ __align__(16) __half2 g_ab[(size_t)NF * 128];   // (a,b) per (f,j)  32 MiB
__device__ __align__(16) float2  g_comp [NCH * 128];
__device__ __align__(16) float   g_carry[NCH * 128];
__device__ __align__(16) __half  g_zhi[(size_t)NF * 128];  // 16 MiB
__device__ __align__(16) __half  g_zlo[(size_t)NF * 128];  // 16 MiB
__device__ __align__(16) __half  g_w1p[8 * 256 * 64];      // chunked, row-permuted
__device__ __align__(16) __half  g_w2p[256 * 128];

// ===========================================================================
// Helpers
// ===========================================================================
__device__ __forceinline__ uint32_t smem_u32(const void* p) {
    uint32_t a;
    asm("{ .reg .u64 t; cvta.to.shared.u64 t, %1; cvt.u32.u64 %0, t; }" : "=r"(a) : "l"(p));
    return a;
}
__device__ __forceinline__ void cpa16(uint32_t s, const void* g) {
    asm volatile("cp.async.cg.shared.global [%0], [%1], 16;"
                 :: "r"(s), "l"(__cvta_generic_to_global(g)));
}
#define CPA_COMMIT()  asm volatile("cp.async.commit_group;" ::: "memory")
#define CPA_WAIT(n)   asm volatile("cp.async.wait_group %0;" :: "n"(n) : "memory")

// m16n8k16 row.col f32.f16.f16.f32 (sm_80+, works on plain sm_103 target)
__device__ __forceinline__ void mma16816(float* c, const uint32_t* a, const uint32_t* b) {
    asm volatile(
        "mma.sync.aligned.m16n8k16.row.col.f32.f16.f16.f32 "
        "{%0,%1,%2,%3}, {%4,%5,%6,%7}, {%8,%9}, {%0,%1,%2,%3};"
        : "+f"(c[0]), "+f"(c[1]), "+f"(c[2]), "+f"(c[3])
        : "r"(a[0]), "r"(a[1]), "r"(a[2]), "r"(a[3]), "r"(b[0]), "r"(b[1]));
}
__device__ __forceinline__ uint32_t pack_h2(__half a, __half b) {
    __half2 h = __halves2half2(a, b);
    return *(uint32_t*)&h;
}
__device__ __forceinline__ int perm_n(int n) {   // interleave j / j+128
    return (n & 1) ? 128 + (n >> 1) : (n >> 1);
}
__device__ __forceinline__ float sigm(float x) { return 1.f / (1.f + __expf(-x)); }

// ===========================================================================
// Prep: W1 -> fp16, rows permuted, chunked [8c][256n'][64k]
// ===========================================================================
__global__ void k_prep_w1(const float* __restrict__ W1)
{
    int idx = blockIdx.x * 256 + threadIdx.x;
    if (idx >= 256 * 512) return;
    int np = idx >> 9, k = idx & 511;
    float v = W1[perm_n(np) * 512 + k];
    g_w1p[(k >> 6) * 16384 + np * 64 + (k & 63)] = __float2half_rn(v);
}
__global__ void k_prep_w2(const float* __restrict__ W2)
{
    int idx = blockIdx.x * 256 + threadIdx.x;
    if (idx >= 256 * 128) return;
    g_w2p[idx] = __float2half_rn(W2[idx]);
}

// ===========================================================================
// GEMM1: D[f 128][n' 128] = x^T * W1p^T (2-product fp16 split, f32 accum)
// Epilogue: adjacent cols = (left j, right j) -> (a,b) half2, thread-local.
// smem: x fp32 [2][64][132], W fp16 [2][128][72], B1 perm [128] f32
// ===========================================================================
#define SM1_X0   0
#define SM1_X1   33792
#define SM1_W0   67584
#define SM1_W1   86016
#define SM1_B1   104448
#define SM1_SIZE 104960

__global__ void __launch_bounds__(256)
k_gemm1(const float* __restrict__ inp, const float* __restrict__ B1)
{
    extern __shared__ char smem[];
    const uint32_t sb = smem_u32(smem);
    const int tid = threadIdx.x, lane = tid & 31, wid = tid >> 5;
    const int g = lane >> 2, t = lane & 3;
    const int fw = (wid & 3) * 32, nw = (wid >> 2) * 64;
    const int f0 = blockIdx.x * 128, n0 = blockIdx.y * 128;

    if (tid < 128) ((float*)(smem + SM1_B1))[tid] = B1[perm_n(n0 + tid)];

    float acc[2][8][4];
    #pragma unroll
    for (int a = 0; a < 2; a++)
        #pragma unroll
        for (int b = 0; b < 8; b++)
            #pragma unroll
            for (int q = 0; q < 4; q++) acc[a][b][q] = 0.f;

    auto load_chunk = [&](int c, int buf) {
        uint32_t xs = sb + (buf ? SM1_X1 : SM1_X0);
        const char* xg = (const char*)inp + ((size_t)(c * 64) * NF + f0) * 4;
        #pragma unroll
        for (int i = tid; i < 2048; i += 256)
            cpa16(xs + (i >> 5) * 528 + (i & 31) * 16,
                  xg + (size_t)(i >> 5) * (NF * 4) + (i & 31) * 16);
        uint32_t wsm = sb + (buf ? SM1_W1 : SM1_W0);
        const char* wg = (const char*)g_w1p + ((size_t)c * 16384 + (size_t)n0 * 64) * 2;
        #pragma unroll
        for (int i = tid; i < 1024; i += 256)
            cpa16(wsm + (i >> 3) * 144 + (i & 7) * 16, wg + i * 16);
    };

    load_chunk(0, 0);
    CPA_COMMIT();

    for (int c = 0; c < 8; c++) {
        const int buf = c & 1;
        if (c < 7) { load_chunk(c + 1, buf ^ 1); CPA_COMMIT(); CPA_WAIT(1); }
        else       { CPA_WAIT(0); }
        __syncthreads();

        const float*  xs = (const float*)(smem + (buf ? SM1_X1 : SM1_X0));
        const __half* ws = (const __half*)(smem + (buf ? SM1_W1 : SM1_W0));

        #pragma unroll
        for (int ks = 0; ks < 4; ks++) {
            uint32_t ahi[2][4], alo[2][4];
            #pragma unroll
            for (int mt = 0; mt < 2; mt++)
                #pragma unroll
                for (int r = 0; r < 4; r++) {
                    int row = fw + mt * 16 + g + ((r & 1) << 3);
                    int kc  = ks * 16 + 2 * t + ((r >> 1) << 3);
                    float v0 = xs[kc * 132 + row];
                    float v1 = xs[(kc + 1) * 132 + row];
                    __half h0 = __float2half_rn(v0), h1 = __float2half_rn(v1);
                    __half l0 = __float2half_rn(v0 - __half2float(h0));
                    __half l1 = __float2half_rn(v1 - __half2float(h1));
                    ahi[mt][r] = pack_h2(h0, h1);
                    alo[mt][r] = pack_h2(l0, l1);
                }
            uint32_t bb[8][2];
            #pragma unroll
            for (int nt = 0; nt < 8; nt++) {
                const __half* wp = ws + (nw + nt * 8 + g) * 72 + ks * 16 + 2 * t;
                bb[nt][0] = *(const uint32_t*)wp;
                bb[nt][1] = *(const uint32_t*)(wp + 8);
            }
            #pragma unroll
            for (int mt = 0; mt < 2; mt++)
                #pragma unroll
                for (int nt = 0; nt < 8; nt++) {
                    mma16816(acc[mt][nt], ahi[mt], bb[nt]);
                    mma16816(acc[mt][nt], alo[mt], bb[nt]);
                }
        }
        __syncthreads();
    }

    const float* sB1 = (const float*)(smem + SM1_B1);
    #pragma unroll
    for (int mt = 0; mt < 2; mt++)
        #pragma unroll
        for (int nt = 0; nt < 8; nt++) {
            int fl  = fw + mt * 16 + g;
            int nl  = nw + nt * 8 + 2 * t;
            int j   = (n0 + nl) >> 1;
            float b0 = sB1[nl], b1 = sB1[nl + 1];
            const float* cc = acc[mt][nt];
            float h0 = sigm(cc[0] + b0), h1 = sigm(cc[1] + b1);
            g_ab[(size_t)(f0 + fl) * 128 + j] = __floats2half2_rn(h0 * h1, 1.f - h0);
            h0 = sigm(cc[2] + b0); h1 = sigm(cc[3] + b1);
            g_ab[(size_t)(f0 + fl + 8) * 128 + j] = __floats2half2_rn(h0 * h1, 1.f - h0);
        }
}

// ===========================================================================
// Scan: s' = a*s + b per lane j, 65535 steps. 3-phase parallel scan.
// ===========================================================================
__global__ void __launch_bounds__(128) k_scan_chunks()
{
    const int c = blockIdx.x, j = threadIdx.x;
    const int t0 = c * CHUNK;
    const int n = min(CHUNK, TSCAN - t0);
    const __half2* p = g_ab + (size_t)t0 * 128 + j;
    float A = 1.f, B = 0.f;
    #pragma unroll 8
    for (int t = 0; t < n; t++) {
        float2 v = __half22float2(p[(size_t)t * 128]);
        B = fmaf(v.x, B, v.y);
        A *= v.x;
    }
    g_comp[c * 128 + j] = make_float2(A, B);
}

__global__ void __launch_bounds__(1024) k_scan_carry()
{
    __shared__ float As[2][NCH], Bs[2][NCH];
    const int j = blockIdx.x, c = threadIdx.x;
    float2 v = g_comp[c * 128 + j];
    As[0][c] = v.x; Bs[0][c] = v.y;
    int src = 0;
    #pragma unroll
    for (int d = 1; d < NCH; d <<= 1) {
        __syncthreads();
        float A = As[src][c], B = Bs[src][c];
        if (c >= d) {
            float Ap = As[src][c - d], Bp = Bs[src][c - d];
            B = fmaf(A, Bp, B);
            A = A * Ap;
        }
        As[src ^ 1][c] = A; Bs[src ^ 1][c] = B;
        src ^= 1;
    }
    __syncthreads();
    g_carry[c * 128 + j] = c ? Bs[src][c - 1] : 0.f;
}

__global__ void __launch_bounds__(128) k_scan_apply()
{
    const int c = blockIdx.x, j = threadIdx.x;
    const int t0 = c * CHUNK;
    const int n = min(CHUNK, TSCAN - t0);
    float s = g_carry[c * 128 + j];
    if (c == 0) { g_zhi[j] = __float2half_rn(0.f); g_zlo[j] = __float2half_rn(0.f); }
    const __half2* p = g_ab + (size_t)t0 * 128 + j;
    __half* zh = g_zhi + (size_t)(t0 + 1) * 128 + j;
    __half* zl = g_zlo + (size_t)(t0 + 1) * 128 + j;
    #pragma unroll 4
    for (int t = 0; t < n; t++) {
        float2 v = __half22float2(p[(size_t)t * 128]);
        s = fmaf(v.x, s, v.y);
        __half hh = __float2half_rn(s);
        zh[(size_t)t * 128] = hh;
        zl[(size_t)t * 128] = __float2half_rn(s - __half2float(hh));
    }
}

// ===========================================================================
// GEMM2: out[n][f] = 1 - sigmoid(W2 @ z + B2), z fp16 hi/lo, W2 fp16 hi.
// smem: zhi/zlo [128][136] f16, W2 [128][136] f16, B2 [128] f32
// ===========================================================================
#define SM2_ZH   0
#define SM2_ZL   34816
#define SM2_W    69632
#define SM2_B2   104448
#define SM2_SIZE 104960

__global__ void __launch_bounds__(256)
k_gemm2(const float* __restrict__ B2, float* __restrict__ out)
{
    extern __shared__ char smem[];
    const uint32_t sb = smem_u32(smem);
    const int tid = threadIdx.x, lane = tid & 31, wid = tid >> 5;
    const int g = lane >> 2, t = lane & 3;
    const int fw = (wid & 3) * 32, nw = (wid >> 2) * 64;
    const int f0 = blockIdx.x * 128, n0 = blockIdx.y * 128;

    if (tid < 128) ((float*)(smem + SM2_B2))[tid] = B2[n0 + tid];

    {
        const char* zh = (const char*)g_zhi + (size_t)f0 * 256;
        const char* zl = (const char*)g_zlo + (size_t)f0 * 256;
        const char* wg = (const char*)g_w2p + (size_t)n0 * 256;
        #pragma unroll
        for (int i = tid; i < 2048; i += 256) {
            uint32_t so = (i >> 4) * 272 + (i & 15) * 16;
            cpa16(sb + SM2_ZH + so, zh + i * 16);
            cpa16(sb + SM2_ZL + so, zl + i * 16);
            cpa16(sb + SM2_W  + so, wg + i * 16);
        }
        CPA_COMMIT();
        CPA_WAIT(0);
    }
    __syncthreads();

    const __half* szh = (const __half*)(smem + SM2_ZH);
    const __half* szl = (const __half*)(smem + SM2_ZL);
    const __half* sw  = (const __half*)(smem + SM2_W);

    float acc[2][8][4];
    #pragma unroll
    for (int a = 0; a < 2; a++)
        #pragma unroll
        for (int b = 0; b < 8; b++)
            #pragma unroll
            for (int q = 0; q < 4; q++) acc[a][b][q] = 0.f;

    #pragma unroll
    for (int ks = 0; ks < 8; ks++) {
        uint32_t ahi[2][4], alo[2][4];
        #pragma unroll
        for (int mt = 0; mt < 2; mt++)
            #pragma unroll
            for (int r = 0; r < 4; r++) {
                int row = fw + mt * 16 + g + ((r & 1) << 3);
                int kc  = ks * 16 + 2 * t + ((r >> 1) << 3);
                ahi[mt][r] = *(const uint32_t*)(szh + row * 136 + kc);
                alo[mt][r] = *(const uint32_t*)(szl + row * 136 + kc);
            }
        uint32_t bb[8][2];
        #pragma unroll
        for (int nt = 0; nt < 8; nt++) {
            const __half* wp = sw + (nw + nt * 8 + g) * 136 + ks * 16 + 2 * t;
            bb[nt][0] = *(const uint32_t*)wp;
            bb[nt][1] = *(const uint32_t*)(wp + 8);
        }
        #pragma unroll
        for (int mt = 0; mt < 2; mt++)
            #pragma unroll
            for (int nt = 0; nt < 8; nt++) {
                mma16816(acc[mt][nt], ahi[mt], bb[nt]);
                mma16816(acc[mt][nt], alo[mt], bb[nt]);
            }
    }

    const float* sB2 = (const float*)(smem + SM2_B2);
    #pragma unroll
    for (int mt = 0; mt < 2; mt++)
        #pragma unroll
        for (int nt = 0; nt < 8; nt++) {
            int fl = fw + mt * 16 + g;
            int nl = nw + nt * 8 + 2 * t;
            const float* cc = acc[mt][nt];
            float b0 = sB2[nl], b1 = sB2[nl + 1];
            out[(size_t)(n0 + nl)     * NF + f0 + fl]     = 1.f / (1.f + __expf(cc[0] + b0));
            out[(size_t)(n0 + nl + 1) * NF + f0 + fl]     = 1.f / (1.f + __expf(cc[1] + b1));
            out[(size_t)(n0 + nl)     * NF + f0 + fl + 8] = 1.f / (1.f + __expf(cc[2] + b0));
            out[(size_t)(n0 + nl + 1) * NF + f0 + fl + 8] = 1.f / (1.f + __expf(cc[3] + b1));
        }
}

// ===========================================================================
extern "C" void kernel_launch(void* const* d_in, const int* in_sizes, int n_in,
                              void* d_out, int out_size)
{
    const float* inp = (const float*)d_in[0];   // (512, 65536)
    const float* W1  = (const float*)d_in[1];   // (256, 512)
    const float* B1  = (const float*)d_in[2];   // (256, 1)
    const float* W2  = (const float*)d_in[3];   // (256, 128)
    const float* B2  = (const float*)d_in[4];   // (256, 1)
    float* out = (float*)d_out;                 // (256, 65536)

    cudaFuncSetAttribute(k_gemm1, cudaFuncAttributeMaxDynamicSharedMemorySize, SM1_SIZE);
    cudaFuncSetAttribute(k_gemm2, cudaFuncAttributeMaxDynamicSharedMemorySize, SM2_SIZE);

    k_prep_w1<<<512, 256>>>(W1);
    k_prep_w2<<<128, 256>>>(W2);
    k_gemm1<<<dim3(NF / 128, 2), 256, SM1_SIZE>>>(inp, B1);
    k_scan_chunks<<<NCH, 128>>>();
    k_scan_carry<<<128, NCH>>>();
    k_scan_apply<<<NCH, 128>>>();
    k_gemm2<<<dim3(NF / 128, 2), 256, SM2_SIZE>>>(B2, out);
}

// round 8
// speedup vs baseline: 3.6306x; 1.5184x over previous
#include <cuda_runtime.h>
#include <cuda_fp16.h>
#include <cstdint>

#define NF     65536
#define TSCAN  65535
#define CHUNK  32
#define NCH    2048

// ===========================================================================
// Device scratch (no runtime allocation allowed)
// ===========================================================================
__device__ __align__(16) __half2 g_ab[(size_t)NF * 128];   // (a,b) per (f,j)  32 MiB
__device__ __align__(16) float2  g_comp [NCH * 128];
__device__ __align__(16) float   g_carry[NCH * 128];
__device__ __align__(16) __half  g_zhi[(size_t)NF * 128];  // 16 MiB
__device__ __align__(16) __half  g_zlo[(size_t)NF * 128];  // 16 MiB
__device__ __align__(16) __half  g_w1p[8 * 256 * 64];      // chunked, row-permuted
__device__ __align__(16) __half  g_w2p[256 * 128];

// ===========================================================================
// Helpers
// ===========================================================================
__device__ __forceinline__ uint32_t smem_u32(const void* p) {
    uint32_t a;
    asm("{ .reg .u64 t; cvta.to.shared.u64 t, %1; cvt.u32.u64 %0, t; }" : "=r"(a) : "l"(p));
    return a;
}
__device__ __forceinline__ void cpa16(uint32_t s, const void* g) {
    asm volatile("cp.async.cg.shared.global [%0], [%1], 16;"
                 :: "r"(s), "l"(__cvta_generic_to_global(g)));
}
#define CPA_COMMIT()  asm volatile("cp.async.commit_group;" ::: "memory")
#define CPA_WAIT(n)   asm volatile("cp.async.wait_group %0;" :: "n"(n) : "memory")

__device__ __forceinline__ void mma16816(float* c, const uint32_t* a, const uint32_t* b) {
    asm volatile(
        "mma.sync.aligned.m16n8k16.row.col.f32.f16.f16.f32 "
        "{%0,%1,%2,%3}, {%4,%5,%6,%7}, {%8,%9}, {%0,%1,%2,%3};"
        : "+f"(c[0]), "+f"(c[1]), "+f"(c[2]), "+f"(c[3])
        : "r"(a[0]), "r"(a[1]), "r"(a[2]), "r"(a[3]), "r"(b[0]), "r"(b[1]));
}
__device__ __forceinline__ uint32_t pack_h2(__half a, __half b) {
    __half2 h = __halves2half2(a, b);
    return *(uint32_t*)&h;
}
__device__ __forceinline__ int perm_n(int n) {   // interleave j / j+128
    return (n & 1) ? 128 + (n >> 1) : (n >> 1);
}
__device__ __forceinline__ float sigm(float x) { return 1.f / (1.f + __expf(-x)); }

// ===========================================================================
// Prep: W1 -> fp16, rows permuted, chunked [8c][256n'][64k];  W2 -> fp16
// ===========================================================================
__global__ void k_prep_w1(const float* __restrict__ W1)
{
    int idx = blockIdx.x * 256 + threadIdx.x;
    if (idx >= 256 * 512) return;
    int np = idx >> 9, k = idx & 511;
    float v = W1[perm_n(np) * 512 + k];
    g_w1p[(k >> 6) * 16384 + np * 64 + (k & 63)] = __float2half_rn(v);
}
__global__ void k_prep_w2(const float* __restrict__ W2)
{
    int idx = blockIdx.x * 256 + threadIdx.x;
    if (idx >= 256 * 128) return;
    g_w2p[idx] = __float2half_rn(W2[idx]);
}

// ===========================================================================
// GEMM1: D[f 128][n' 256] = x^T * W1p^T (2-product fp16 split, f32 accum)
// 512 threads, warps = 4(f) x 4(n). Convert-once pass builds fp16 hi/lo planes.
// smem: stage f32 [64][132] | planes [2][128][72] hi+lo | W [2][256][72] | B1
// ===========================================================================
#define SM1_STAGE 0
#define SM1_XHI   33792
#define SM1_XLO   70656
#define SM1_W     107520
#define SM1_B1    181248
#define SM1_SIZE  182272

__global__ void __launch_bounds__(512)
k_gemm1(const float* __restrict__ inp, const float* __restrict__ B1)
{
    extern __shared__ char smem[];
    const uint32_t sb = smem_u32(smem);
    const int tid = threadIdx.x, lane = tid & 31, wid = tid >> 5;
    const int g = lane >> 2, t = lane & 3;
    const int fw = (wid & 3) * 32, nw = (wid >> 2) * 64;
    const int f0 = blockIdx.x * 128;

    if (tid < 256) ((float*)(smem + SM1_B1))[tid] = B1[perm_n(tid)];

    float acc[2][8][4];
    #pragma unroll
    for (int a = 0; a < 2; a++)
        #pragma unroll
        for (int b = 0; b < 8; b++)
            #pragma unroll
            for (int q = 0; q < 4; q++) acc[a][b][q] = 0.f;

    auto load_chunk = [&](int c, int wbuf) {
        const char* xg = (const char*)inp + ((size_t)(c * 64) * NF + f0) * 4;
        #pragma unroll
        for (int i = tid; i < 2048; i += 512)
            cpa16(sb + SM1_STAGE + (i >> 5) * 528 + (i & 31) * 16,
                  xg + (size_t)(i >> 5) * (NF * 4) + (i & 31) * 16);
        const char* wg = (const char*)g_w1p + (size_t)c * 32768;
        #pragma unroll
        for (int i = tid; i < 2048; i += 512)
            cpa16(sb + SM1_W + wbuf * 36864 + (i >> 3) * 144 + (i & 7) * 16,
                  wg + i * 16);
    };

    load_chunk(0, 0);
    CPA_COMMIT();

    const int fcv = tid & 127, kg = tid >> 7;     // convert-pass assignment

    for (int c = 0; c < 8; c++) {
        const int buf = c & 1;
        CPA_WAIT(0);
        __syncthreads();                           // stage+W ready; mma(c-1) done

        {   // convert stage -> fp16 hi/lo planes (each element exactly once)
            const float* st = (const float*)(smem + SM1_STAGE);
            __half* xh = (__half*)(smem + SM1_XHI + buf * 18432);
            __half* xl = (__half*)(smem + SM1_XLO + buf * 18432);
            #pragma unroll
            for (int kk = 0; kk < 16; kk += 2) {
                int k = kg * 16 + kk;
                float v0 = st[k * 132 + fcv];
                float v1 = st[(k + 1) * 132 + fcv];
                __half h0 = __float2half_rn(v0), h1 = __float2half_rn(v1);
                __half l0 = __float2half_rn(v0 - __half2float(h0));
                __half l1 = __float2half_rn(v1 - __half2float(h1));
                *(uint32_t*)(xh + fcv * 72 + k) = pack_h2(h0, h1);
                *(uint32_t*)(xl + fcv * 72 + k) = pack_h2(l0, l1);
            }
        }
        __syncthreads();                           // planes ready; stage free

        if (c < 7) { load_chunk(c + 1, buf ^ 1); CPA_COMMIT(); }

        const __half* xh = (const __half*)(smem + SM1_XHI + buf * 18432);
        const __half* xl = (const __half*)(smem + SM1_XLO + buf * 18432);
        const __half* ws = (const __half*)(smem + SM1_W + buf * 36864);

        #pragma unroll
        for (int ks = 0; ks < 4; ks++) {
            uint32_t ahi[2][4], alo[2][4];
            #pragma unroll
            for (int mt = 0; mt < 2; mt++)
                #pragma unroll
                for (int r = 0; r < 4; r++) {
                    int row = fw + mt * 16 + g + ((r & 1) << 3);
                    int kc  = ks * 16 + 2 * t + ((r >> 1) << 3);
                    ahi[mt][r] = *(const uint32_t*)(xh + row * 72 + kc);
                    alo[mt][r] = *(const uint32_t*)(xl + row * 72 + kc);
                }
            uint32_t bb[8][2];
            #pragma unroll
            for (int nt = 0; nt < 8; nt++) {
                const __half* wp = ws + (nw + nt * 8 + g) * 72 + ks * 16 + 2 * t;
                bb[nt][0] = *(const uint32_t*)wp;
                bb[nt][1] = *(const uint32_t*)(wp + 8);
            }
            #pragma unroll
            for (int mt = 0; mt < 2; mt++)
                #pragma unroll
                for (int nt = 0; nt < 8; nt++) {
                    mma16816(acc[mt][nt], ahi[mt], bb[nt]);
                    mma16816(acc[mt][nt], alo[mt], bb[nt]);
                }
        }
    }

    // Epilogue: sigmoid+gate -> stage (a,b) half2 in smem, then coalesced copy.
    __syncthreads();
    const float* sB1 = (const float*)(smem + SM1_B1);
    __half2* sAB = (__half2*)smem;                 // [128 f][pitch 132]
    #pragma unroll
    for (int mt = 0; mt < 2; mt++)
        #pragma unroll
        for (int nt = 0; nt < 8; nt++) {
            int fl = fw + mt * 16 + g;
            int nl = nw + nt * 8 + 2 * t;
            int j  = nl >> 1;
            float b0 = sB1[nl], b1 = sB1[nl + 1];
            const float* cc = acc[mt][nt];
            float h0 = sigm(cc[0] + b0), h1 = sigm(cc[1] + b1);
            sAB[fl * 132 + j] = __floats2half2_rn(h0 * h1, 1.f - h0);
            h0 = sigm(cc[2] + b0); h1 = sigm(cc[3] + b1);
            sAB[(fl + 8) * 132 + j] = __floats2half2_rn(h0 * h1, 1.f - h0);
        }
    __syncthreads();
    const float4* s4 = (const float4*)smem;
    float4* g4 = (float4*)(g_ab + (size_t)f0 * 128);
    #pragma unroll
    for (int i = tid; i < 4096; i += 512)
        g4[i] = s4[(i >> 5) * 33 + (i & 31)];
}

// ===========================================================================
// Scan: s' = a*s + b per lane j, 65535 steps. 3-phase parallel scan.
// ===========================================================================
__global__ void __launch_bounds__(128) k_scan_chunks()
{
    const int c = blockIdx.x, j = threadIdx.x;
    const int t0 = c * CHUNK;
    const int n = min(CHUNK, TSCAN - t0);
    const __half2* p = g_ab + (size_t)t0 * 128 + j;
    float A = 1.f, B = 0.f;
    #pragma unroll 8
    for (int t = 0; t < n; t++) {
        float2 v = __half22float2(p[(size_t)t * 128]);
        B = fmaf(v.x, B, v.y);
        A *= v.x;
    }
    g_comp[c * 128 + j] = make_float2(A, B);
}

__global__ void __launch_bounds__(1024) k_scan_carry()
{
    __shared__ float As[2][1024], Bs[2][1024];
    const int j = blockIdx.x, c = threadIdx.x;
    float2 v0 = g_comp[(2 * c)     * 128 + j];
    float2 v1 = g_comp[(2 * c + 1) * 128 + j];
    float A = v1.x * v0.x;
    float B = fmaf(v1.x, v0.y, v1.y);
    As[0][c] = A; Bs[0][c] = B;
    int src = 0;
    #pragma unroll
    for (int d = 1; d < 1024; d <<= 1) {
        __syncthreads();
        float a = As[src][c], b = Bs[src][c];
        if (c >= d) {
            b = fmaf(a, Bs[src][c - d], b);
            a = a * As[src][c - d];
        }
        As[src ^ 1][c] = a; Bs[src ^ 1][c] = b;
        src ^= 1;
    }
    __syncthreads();
    float exB = c ? Bs[src][c - 1] : 0.f;          // state entering chunk 2c
    g_carry[(2 * c)     * 128 + j] = exB;
    g_carry[(2 * c + 1) * 128 + j] = fmaf(v0.x, exB, v0.y);
}

__global__ void __launch_bounds__(128) k_scan_apply()
{
    const int c = blockIdx.x, j = threadIdx.x;
    const int t0 = c * CHUNK;
    const int n = min(CHUNK, TSCAN - t0);
    float s = g_carry[c * 128 + j];
    if (c == 0) { g_zhi[j] = __float2half_rn(0.f); g_zlo[j] = __float2half_rn(0.f); }
    const __half2* p = g_ab + (size_t)t0 * 128 + j;
    __half* zh = g_zhi + (size_t)(t0 + 1) * 128 + j;
    __half* zl = g_zlo + (size_t)(t0 + 1) * 128 + j;
    #pragma unroll 4
    for (int t = 0; t < n; t++) {
        float2 v = __half22float2(p[(size_t)t * 128]);
        s = fmaf(v.x, s, v.y);
        __half hh = __float2half_rn(s);
        zh[(size_t)t * 128] = hh;
        zl[(size_t)t * 128] = __float2half_rn(s - __half2float(hh));
    }
}

// ===========================================================================
// GEMM2: out[n 256][f 128] = 1 - sigmoid(W2 @ z + B2). 512 threads, 4f x 4n.
// smem: zhi/zlo [128][136] f16, W2 [256][136] f16, B2 [256] f32
// ===========================================================================
#define SM2_ZH   0
#define SM2_ZL   34816
#define SM2_W    69632
#define SM2_B2   139264
#define SM2_SIZE 140288

__global__ void __launch_bounds__(512)
k_gemm2(const float* __restrict__ B2, float* __restrict__ out)
{
    extern __shared__ char smem[];
    const uint32_t sb = smem_u32(smem);
    const int tid = threadIdx.x, lane = tid & 31, wid = tid >> 5;
    const int g = lane >> 2, t = lane & 3;
    const int fw = (wid & 3) * 32, nw = (wid >> 2) * 64;
    const int f0 = blockIdx.x * 128;

    if (tid < 256) ((float*)(smem + SM2_B2))[tid] = B2[tid];

    {
        const char* zh = (const char*)g_zhi + (size_t)f0 * 256;
        const char* zl = (const char*)g_zlo + (size_t)f0 * 256;
        const char* wg = (const char*)g_w2p;
        #pragma unroll
        for (int i = tid; i < 2048; i += 512) {
            uint32_t so = (i >> 4) * 272 + (i & 15) * 16;
            cpa16(sb + SM2_ZH + so, zh + i * 16);
            cpa16(sb + SM2_ZL + so, zl + i * 16);
        }
        #pragma unroll
        for (int i = tid; i < 4096; i += 512)
            cpa16(sb + SM2_W + (i >> 4) * 272 + (i & 15) * 16, wg + i * 16);
        CPA_COMMIT();
        CPA_WAIT(0);
    }
    __syncthreads();

    const __half* szh = (const __half*)(smem + SM2_ZH);
    const __half* szl = (const __half*)(smem + SM2_ZL);
    const __half* sw  = (const __half*)(smem + SM2_W);

    float acc[2][8][4];
    #pragma unroll
    for (int a = 0; a < 2; a++)
        #pragma unroll
        for (int b = 0; b < 8; b++)
            #pragma unroll
            for (int q = 0; q < 4; q++) acc[a][b][q] = 0.f;

    #pragma unroll
    for (int ks = 0; ks < 8; ks++) {
        uint32_t ahi[2][4], alo[2][4];
        #pragma unroll
        for (int mt = 0; mt < 2; mt++)
            #pragma unroll
            for (int r = 0; r < 4; r++) {
                int row = fw + mt * 16 + g + ((r & 1) << 3);
                int kc  = ks * 16 + 2 * t + ((r >> 1) << 3);
                ahi[mt][r] = *(const uint32_t*)(szh + row * 136 + kc);
                alo[mt][r] = *(const uint32_t*)(szl + row * 136 + kc);
            }
        uint32_t bb[8][2];
        #pragma unroll
        for (int nt = 0; nt < 8; nt++) {
            const __half* wp = sw + (nw + nt * 8 + g) * 136 + ks * 16 + 2 * t;
            bb[nt][0] = *(const uint32_t*)wp;
            bb[nt][1] = *(const uint32_t*)(wp + 8);
        }
        #pragma unroll
        for (int mt = 0; mt < 2; mt++)
            #pragma unroll
            for (int nt = 0; nt < 8; nt++) {
                mma16816(acc[mt][nt], ahi[mt], bb[nt]);
                mma16816(acc[mt][nt], alo[mt], bb[nt]);
            }
    }

    const float* sB2 = (const float*)(smem + SM2_B2);
    #pragma unroll
    for (int mt = 0; mt < 2; mt++)
        #pragma unroll
        for (int nt = 0; nt < 8; nt++) {
            int fl = fw + mt * 16 + g;
            int nl = nw + nt * 8 + 2 * t;
            const float* cc = acc[mt][nt];
            float b0 = sB2[nl], b1 = sB2[nl + 1];
            out[(size_t)nl       * NF + f0 + fl]     = 1.f / (1.f + __expf(cc[0] + b0));
            out[(size_t)(nl + 1) * NF + f0 + fl]     = 1.f / (1.f + __expf(cc[1] + b1));
            out[(size_t)nl       * NF + f0 + fl + 8] = 1.f / (1.f + __expf(cc[2] + b0));
            out[(size_t)(nl + 1) * NF + f0 + fl + 8] = 1.f / (1.f + __expf(cc[3] + b1));
        }
}

// ===========================================================================
extern "C" void kernel_launch(void* const* d_in, const int* in_sizes, int n_in,
                              void* d_out, int out_size)
{
    const float* inp = (const float*)d_in[0];   // (512, 65536)
    const float* W1  = (const float*)d_in[1];   // (256, 512)
    const float* B1  = (const float*)d_in[2];   // (256, 1)
    const float* W2  = (const float*)d_in[3];   // (256, 128)
    const float* B2  = (const float*)d_in[4];   // (256, 1)
    float* out = (float*)d_out;                 // (256, 65536)

    cudaFuncSetAttribute(k_gemm1, cudaFuncAttributeMaxDynamicSharedMemorySize, SM1_SIZE);
    cudaFuncSetAttribute(k_gemm2, cudaFuncAttributeMaxDynamicSharedMemorySize, SM2_SIZE);

    k_prep_w1<<<512, 256>>>(W1);
    k_prep_w2<<<128, 256>>>(W2);
    k_gemm1<<<NF / 128, 512, SM1_SIZE>>>(inp, B1);
    k_scan_chunks<<<NCH, 128>>>();
    k_scan_carry<<<128, 1024>>>();
    k_scan_apply<<<NCH, 128>>>();
    k_gemm2<<<NF / 128, 512, SM2_SIZE>>>(B2, out);
}

// round 13
// speedup vs baseline: 4.8408x; 1.3333x over previous
#include <cuda_runtime.h>
#include <cuda_fp16.h>
#include <cstdint>

#define NF     65536
#define TSCAN  65535
#define CHUNK  32
#define NCH    2048

// ===========================================================================
// Device scratch (no runtime allocation allowed)
// ===========================================================================
__device__ __align__(16) __half2 g_ab[(size_t)NF * 128];   // (a,b) per (f,j)  32 MiB
__device__ __align__(16) float2  g_comp [NCH * 128];
__device__ __align__(16) float   g_carry[NCH * 128];
__device__ __align__(16) __half  g_w1p[8 * 256 * 64];      // chunked, row-permuted
__device__ __align__(16) __half  g_w2p[256 * 128];

// ===========================================================================
// Helpers
// ===========================================================================
__device__ __forceinline__ uint32_t smem_u32(const void* p) {
    uint32_t a;
    asm("{ .reg .u64 t; cvta.to.shared.u64 t, %1; cvt.u32.u64 %0, t; }" : "=r"(a) : "l"(p));
    return a;
}
__device__ __forceinline__ void cpa16(uint32_t s, const void* g) {
    asm volatile("cp.async.cg.shared.global [%0], [%1], 16;"
                 :: "r"(s), "l"(__cvta_generic_to_global(g)));
}
#define CPA_COMMIT()  asm volatile("cp.async.commit_group;" ::: "memory")
#define CPA_WAIT(n)   asm volatile("cp.async.wait_group %0;" :: "n"(n) : "memory")

__device__ __forceinline__ void mma16816(float* c, const uint32_t* a, const uint32_t* b) {
    asm volatile(
        "mma.sync.aligned.m16n8k16.row.col.f32.f16.f16.f32 "
        "{%0,%1,%2,%3}, {%4,%5,%6,%7}, {%8,%9}, {%0,%1,%2,%3};"
        : "+f"(c[0]), "+f"(c[1]), "+f"(c[2]), "+f"(c[3])
        : "r"(a[0]), "r"(a[1]), "r"(a[2]), "r"(a[3]), "r"(b[0]), "r"(b[1]));
}
__device__ __forceinline__ uint32_t pack_h2(__half a, __half b) {
    __half2 h = __halves2half2(a, b);
    return *(uint32_t*)&h;
}
__device__ __forceinline__ int perm_n(int n) {   // interleave j / j+128
    return (n & 1) ? 128 + (n >> 1) : (n >> 1);
}
__device__ __forceinline__ float sigm(float x) { return 1.f / (1.f + __expf(-x)); }

// ===========================================================================
// Prep: W1 -> fp16, rows permuted, chunked [8c][256n'][64k];  W2 -> fp16
// ===========================================================================
__global__ void k_prep_w1(const float* __restrict__ W1)
{
    int idx = blockIdx.x * 256 + threadIdx.x;
    if (idx >= 256 * 512) return;
    int np = idx >> 9, k = idx & 511;
    float v = W1[perm_n(np) * 512 + k];
    g_w1p[(k >> 6) * 16384 + np * 64 + (k & 63)] = __float2half_rn(v);
}
__global__ void k_prep_w2(const float* __restrict__ W2)
{
    int idx = blockIdx.x * 256 + threadIdx.x;
    if (idx >= 256 * 128) return;
    g_w2p[idx] = __float2half_rn(W2[idx]);
}

// ===========================================================================
// GEMM1: D[f 128][n' 256] = x^T * W1p^T (single fp16 product, f32 accum)
// 512 threads, warps = 4(f) x 4(n). Convert-once pass builds fp16 plane.
// Epilogue: sigmoid+gate -> smem (a,b); coalesced copy to g_ab; chunk
// composites for 4 chunks computed in-block -> g_comp.
// smem: stage f32 [64][132] | xh [2][128][72] | W [2][256][72] | B1
// ===========================================================================
#define SM1_STAGE 0
#define SM1_XH    33792
#define SM1_W     70656
#define SM1_B1    144384
#define SM1_SIZE  145408

__global__ void __launch_bounds__(512)
k_gemm1(const float* __restrict__ inp, const float* __restrict__ B1)
{
    extern __shared__ char smem[];
    const uint32_t sb = smem_u32(smem);
    const int tid = threadIdx.x, lane = tid & 31, wid = tid >> 5;
    const int g = lane >> 2, t = lane & 3;
    const int fw = (wid & 3) * 32, nw = (wid >> 2) * 64;
    const int f0 = blockIdx.x * 128;

    if (tid < 256) ((float*)(smem + SM1_B1))[tid] = B1[perm_n(tid)];

    float acc[2][8][4];
    #pragma unroll
    for (int a = 0; a < 2; a++)
        #pragma unroll
        for (int b = 0; b < 8; b++)
            #pragma unroll
            for (int q = 0; q < 4; q++) acc[a][b][q] = 0.f;

    auto load_chunk = [&](int c, int wbuf) {
        const char* xg = (const char*)inp + ((size_t)(c * 64) * NF + f0) * 4;
        #pragma unroll
        for (int i = tid; i < 2048; i += 512)
            cpa16(sb + SM1_STAGE + (i >> 5) * 528 + (i & 31) * 16,
                  xg + (size_t)(i >> 5) * (NF * 4) + (i & 31) * 16);
        const char* wg = (const char*)g_w1p + (size_t)c * 32768;
        #pragma unroll
        for (int i = tid; i < 2048; i += 512)
            cpa16(sb + SM1_W + wbuf * 36864 + (i >> 3) * 144 + (i & 7) * 16,
                  wg + i * 16);
    };

    load_chunk(0, 0);
    CPA_COMMIT();

    const int fcv = tid & 127, kg = tid >> 7;     // convert-pass assignment

    for (int c = 0; c < 8; c++) {
        const int buf = c & 1;
        CPA_WAIT(0);
        __syncthreads();                           // stage+W ready; mma(c-1) done

        {   // convert stage -> fp16 plane (each element exactly once)
            const float* st = (const float*)(smem + SM1_STAGE);
            __half* xh = (__half*)(smem + SM1_XH + buf * 18432);
            #pragma unroll
            for (int kk = 0; kk < 16; kk += 2) {
                int k = kg * 16 + kk;
                float v0 = st[k * 132 + fcv];
                float v1 = st[(k + 1) * 132 + fcv];
                *(uint32_t*)(xh + fcv * 72 + k) =
                    pack_h2(__float2half_rn(v0), __float2half_rn(v1));
            }
        }
        __syncthreads();                           // plane ready; stage free

        if (c < 7) { load_chunk(c + 1, buf ^ 1); CPA_COMMIT(); }

        const __half* xh = (const __half*)(smem + SM1_XH + buf * 18432);
        const __half* ws = (const __half*)(smem + SM1_W + buf * 36864);

        #pragma unroll
        for (int ks = 0; ks < 4; ks++) {
            uint32_t aa[2][4];
            #pragma unroll
            for (int mt = 0; mt < 2; mt++)
                #pragma unroll
                for (int r = 0; r < 4; r++) {
                    int row = fw + mt * 16 + g + ((r & 1) << 3);
                    int kc  = ks * 16 + 2 * t + ((r >> 1) << 3);
                    aa[mt][r] = *(const uint32_t*)(xh + row * 72 + kc);
                }
            uint32_t bb[8][2];
            #pragma unroll
            for (int nt = 0; nt < 8; nt++) {
                const __half* wp = ws + (nw + nt * 8 + g) * 72 + ks * 16 + 2 * t;
                bb[nt][0] = *(const uint32_t*)wp;
                bb[nt][1] = *(const uint32_t*)(wp + 8);
            }
            #pragma unroll
            for (int mt = 0; mt < 2; mt++)
                #pragma unroll
                for (int nt = 0; nt < 8; nt++)
                    mma16816(acc[mt][nt], aa[mt], bb[nt]);
        }
    }

    // Epilogue: sigmoid+gate -> stage (a,b) half2 in smem.
    __syncthreads();
    const float* sB1 = (const float*)(smem + SM1_B1);
    __half2* sAB = (__half2*)smem;                 // [128 f][pitch 132]
    #pragma unroll
    for (int mt = 0; mt < 2; mt++)
        #pragma unroll
        for (int nt = 0; nt < 8; nt++) {
            int fl = fw + mt * 16 + g;
            int nl = nw + nt * 8 + 2 * t;
            int j  = nl >> 1;
            float b0 = sB1[nl], b1 = sB1[nl + 1];
            const float* cc = acc[mt][nt];
            float h0 = sigm(cc[0] + b0), h1 = sigm(cc[1] + b1);
            sAB[fl * 132 + j] = __floats2half2_rn(h0 * h1, 1.f - h0);
            h0 = sigm(cc[2] + b0); h1 = sigm(cc[3] + b1);
            sAB[(fl + 8) * 132 + j] = __floats2half2_rn(h0 * h1, 1.f - h0);
        }
    __syncthreads();

    // Coalesced copy to g_ab
    const float4* s4 = (const float4*)smem;
    float4* g4 = (float4*)(g_ab + (size_t)f0 * 128);
    #pragma unroll
    for (int i = tid; i < 4096; i += 512)
        g4[i] = s4[(i >> 5) * 33 + (i & 31)];

    // Fused chunk composites: 4 chunks x 128 lanes = 512 threads
    {
        const int c = tid >> 7, j = tid & 127;
        float A = 1.f, B = 0.f;
        #pragma unroll 8
        for (int tt = 0; tt < 32; tt++) {
            float2 v = __half22float2(sAB[(c * 32 + tt) * 132 + j]);
            B = fmaf(v.x, B, v.y);
            A *= v.x;
        }
        g_comp[(blockIdx.x * 4 + c) * 128 + j] = make_float2(A, B);
    }
}

// ===========================================================================
// Carry scan: state entering each chunk (exclusive), fp32 Hillis-Steele.
// ===========================================================================
__global__ void __launch_bounds__(1024) k_scan_carry()
{
    __shared__ float As[2][1024], Bs[2][1024];
    const int j = blockIdx.x, c = threadIdx.x;
    float2 v0 = g_comp[(2 * c)     * 128 + j];
    float2 v1 = g_comp[(2 * c + 1) * 128 + j];
    float A = v1.x * v0.x;
    float B = fmaf(v1.x, v0.y, v1.y);
    As[0][c] = A; Bs[0][c] = B;
    int src = 0;
    #pragma unroll
    for (int d = 1; d < 1024; d <<= 1) {
        __syncthreads();
        float a = As[src][c], b = Bs[src][c];
        if (c >= d) {
            b = fmaf(a, Bs[src][c - d], b);
            a = a * As[src][c - d];
        }
        As[src ^ 1][c] = a; Bs[src ^ 1][c] = b;
        src ^= 1;
    }
    __syncthreads();
    float exB = c ? Bs[src][c - 1] : 0.f;          // state entering chunk 2c
    g_carry[(2 * c)     * 128 + j] = exB;
    g_carry[(2 * c + 1) * 128 + j] = fmaf(v0.x, exB, v0.y);
}

// ===========================================================================
// GEMM2 (fused apply): per CTA load ab tile, run 4x32-step recurrence in
// smem -> z fp16 plane, then out[n 256][f 128] = 1 - sigmoid(W2 z + B2).
// smem: ab [128][128] half2 (64K) | z [128][136] f16 | W2 [256][136] f16 | B2
// ===========================================================================
#define SM2_AB   0
#define SM2_Z    65536
#define SM2_W    100352
#define SM2_B2   169984
#define SM2_SIZE 171008

__global__ void __launch_bounds__(512)
k_gemm2(const float* __restrict__ B2, float* __restrict__ out)
{
    extern __shared__ char smem[];
    const uint32_t sb = smem_u32(smem);
    const int tid = threadIdx.x, lane = tid & 31, wid = tid >> 5;
    const int g = lane >> 2, t = lane & 3;
    const int fw = (wid & 3) * 32, nw = (wid >> 2) * 64;
    const int f0 = blockIdx.x * 128;

    if (tid < 256) ((float*)(smem + SM2_B2))[tid] = B2[tid];

    {   // ab tile is fully contiguous (64 KB); W2 strided to pitch 136
        const char* ag = (const char*)(g_ab + (size_t)f0 * 128);
        #pragma unroll
        for (int i = tid; i < 4096; i += 512)
            cpa16(sb + SM2_AB + i * 16, ag + i * 16);
        const char* wg = (const char*)g_w2p;
        #pragma unroll
        for (int i = tid; i < 4096; i += 512)
            cpa16(sb + SM2_W + (i >> 4) * 272 + (i & 15) * 16, wg + i * 16);
        CPA_COMMIT();
        CPA_WAIT(0);
    }
    __syncthreads();

    // Fused scan-apply: thread (c = tid>>7, j = tid&127)
    {
        const int c = tid >> 7, j = tid & 127;
        const __half2* ab = (const __half2*)(smem + SM2_AB);
        __half* zs = (__half*)(smem + SM2_Z);
        float s = g_carry[(blockIdx.x * 4 + c) * 128 + j];
        zs[(c * 32) * 136 + j] = __float2half_rn(s);
        #pragma unroll 8
        for (int tt = 0; tt < 31; tt++) {
            float2 v = __half22float2(ab[(c * 32 + tt) * 128 + j]);
            s = fmaf(v.x, s, v.y);
            zs[(c * 32 + tt + 1) * 136 + j] = __float2half_rn(s);
        }
    }
    __syncthreads();

    const __half* sz = (const __half*)(smem + SM2_Z);
    const __half* sw = (const __half*)(smem + SM2_W);

    float acc[2][8][4];
    #pragma unroll
    for (int a = 0; a < 2; a++)
        #pragma unroll
        for (int b = 0; b < 8; b++)
            #pragma unroll
            for (int q = 0; q < 4; q++) acc[a][b][q] = 0.f;

    #pragma unroll
    for (int ks = 0; ks < 8; ks++) {
        uint32_t aa[2][4];
        #pragma unroll
        for (int mt = 0; mt < 2; mt++)
            #pragma unroll
            for (int r = 0; r < 4; r++) {
                int row = fw + mt * 16 + g + ((r & 1) << 3);
                int kc  = ks * 16 + 2 * t + ((r >> 1) << 3);
                aa[mt][r] = *(const uint32_t*)(sz + row * 136 + kc);
            }
        uint32_t bb[8][2];
        #pragma unroll
        for (int nt = 0; nt < 8; nt++) {
            const __half* wp = sw + (nw + nt * 8 + g) * 136 + ks * 16 + 2 * t;
            bb[nt][0] = *(const uint32_t*)wp;
            bb[nt][1] = *(const uint32_t*)(wp + 8);
        }
        #pragma unroll
        for (int mt = 0; mt < 2; mt++)
            #pragma unroll
            for (int nt = 0; nt < 8; nt++)
                mma16816(acc[mt][nt], aa[mt], bb[nt]);
    }

    const float* sB2 = (const float*)(smem + SM2_B2);
    #pragma unroll
    for (int mt = 0; mt < 2; mt++)
        #pragma unroll
        for (int nt = 0; nt < 8; nt++) {
            int fl = fw + mt * 16 + g;
            int nl = nw + nt * 8 + 2 * t;
            const float* cc = acc[mt][nt];
            float b0 = sB2[nl], b1 = sB2[nl + 1];
            out[(size_t)nl       * NF + f0 + fl]     = 1.f / (1.f + __expf(cc[0] + b0));
            out[(size_t)(nl + 1) * NF + f0 + fl]     = 1.f / (1.f + __expf(cc[1] + b1));
            out[(size_t)nl       * NF + f0 + fl + 8] = 1.f / (1.f + __expf(cc[2] + b0));
            out[(size_t)(nl + 1) * NF + f0 + fl + 8] = 1.f / (1.f + __expf(cc[3] + b1));
        }
}

// ===========================================================================
extern "C" void kernel_launch(void* const* d_in, const int* in_sizes, int n_in,
                              void* d_out, int out_size)
{
    const float* inp = (const float*)d_in[0];   // (512, 65536)
    const float* W1  = (const float*)d_in[1];   // (256, 512)
    const float* B1  = (const float*)d_in[2];   // (256, 1)
    const float* W2  = (const float*)d_in[3];   // (256, 128)
    const float* B2  = (const float*)d_in[4];   // (256, 1)
    float* out = (float*)d_out;                 // (256, 65536)

    cudaFuncSetAttribute(k_gemm1, cudaFuncAttributeMaxDynamicSharedMemorySize, SM1_SIZE);
    cudaFuncSetAttribute(k_gemm2, cudaFuncAttributeMaxDynamicSharedMemorySize, SM2_SIZE);

    k_prep_w1<<<512, 256>>>(W1);
    k_prep_w2<<<128, 256>>>(W2);
    k_gemm1<<<NF / 128, 512, SM1_SIZE>>>(inp, B1);
    k_scan_carry<<<128, 1024>>>();
    k_gemm2<<<NF / 128, 512, SM2_SIZE>>>(B2, out);
}

// round 14
// speedup vs baseline: 4.8719x; 1.0064x over previous
#include <cuda_runtime.h>
#include <cuda_fp16.h>
#include <cstdint>

#define NF     65536
#define TSCAN  65535
#define CHUNK  32
#define NCH    2048

// ===========================================================================
// Device scratch (no runtime allocation allowed)
// ===========================================================================
__device__ __align__(16) __half2 g_ab[(size_t)NF * 128];   // (a,b) per (f,j)  32 MiB
__device__ __align__(16) float2  g_comp [NCH * 128];
__device__ __align__(16) float   g_carry[NCH * 128];
__device__ __align__(16) __half  g_w1p[8 * 256 * 64];      // chunked, row-permuted
__device__ __align__(16) __half  g_w2p[256 * 128];

// ===========================================================================
// Helpers
// ===========================================================================
__device__ __forceinline__ uint32_t smem_u32(const void* p) {
    uint32_t a;
    asm("{ .reg .u64 t; cvta.to.shared.u64 t, %1; cvt.u32.u64 %0, t; }" : "=r"(a) : "l"(p));
    return a;
}
__device__ __forceinline__ void cpa16(uint32_t s, const void* g) {
    asm volatile("cp.async.cg.shared.global [%0], [%1], 16;"
                 :: "r"(s), "l"(__cvta_generic_to_global(g)));
}
#define CPA_COMMIT()  asm volatile("cp.async.commit_group;" ::: "memory")
#define CPA_WAIT(n)   asm volatile("cp.async.wait_group %0;" :: "n"(n) : "memory")

__device__ __forceinline__ void mma16816(float* c, const uint32_t* a, const uint32_t* b) {
    asm volatile(
        "mma.sync.aligned.m16n8k16.row.col.f32.f16.f16.f32 "
        "{%0,%1,%2,%3}, {%4,%5,%6,%7}, {%8,%9}, {%0,%1,%2,%3};"
        : "+f"(c[0]), "+f"(c[1]), "+f"(c[2]), "+f"(c[3])
        : "r"(a[0]), "r"(a[1]), "r"(a[2]), "r"(a[3]), "r"(b[0]), "r"(b[1]));
}
__device__ __forceinline__ uint32_t pack_h2(__half a, __half b) {
    __half2 h = __halves2half2(a, b);
    return *(uint32_t*)&h;
}
__device__ __forceinline__ int perm_n(int n) {   // interleave j / j+128
    return (n & 1) ? 128 + (n >> 1) : (n >> 1);
}
__device__ __forceinline__ float sigm(float x) { return 1.f / (1.f + __expf(-x)); }

// ===========================================================================
// Prep: W1 -> fp16, rows permuted, chunked [8c][256n'][64k];  W2 -> fp16
// ===========================================================================
__global__ void k_prep_w1(const float* __restrict__ W1)
{
    int idx = blockIdx.x * 256 + threadIdx.x;
    if (idx >= 256 * 512) return;
    int np = idx >> 9, k = idx & 511;
    float v = W1[perm_n(np) * 512 + k];
    g_w1p[(k >> 6) * 16384 + np * 64 + (k & 63)] = __float2half_rn(v);
}
__global__ void k_prep_w2(const float* __restrict__ W2)
{
    int idx = blockIdx.x * 256 + threadIdx.x;
    if (idx >= 256 * 128) return;
    g_w2p[idx] = __float2half_rn(W2[idx]);
}

// ===========================================================================
// GEMM1: D[f 128][n' 256] = x^T * W1p^T (fp16 product, f32 accum)
// 512 threads, warps = 4(f) x 4(n). All operands double-buffered: next-chunk
// x AND W loads issue at iteration top, covered by convert + MMA.
// smem: stage f32 [2][64][132] | xh [2][128][72] | W [2][256][72] | B1
// ===========================================================================
#define SM1_STAGE 0
#define SM1_XH    67584
#define SM1_W     104448
#define SM1_B1    178176
#define SM1_SIZE  179200

__global__ void __launch_bounds__(512)
k_gemm1(const float* __restrict__ inp, const float* __restrict__ B1)
{
    extern __shared__ char smem[];
    const uint32_t sb = smem_u32(smem);
    const int tid = threadIdx.x, lane = tid & 31, wid = tid >> 5;
    const int g = lane >> 2, t = lane & 3;
    const int fw = (wid & 3) * 32, nw = (wid >> 2) * 64;
    const int f0 = blockIdx.x * 128;

    if (tid < 256) ((float*)(smem + SM1_B1))[tid] = B1[perm_n(tid)];

    float acc[2][8][4];
    #pragma unroll
    for (int a = 0; a < 2; a++)
        #pragma unroll
        for (int b = 0; b < 8; b++)
            #pragma unroll
            for (int q = 0; q < 4; q++) acc[a][b][q] = 0.f;

    auto load_chunk = [&](int c, int buf) {
        const char* xg = (const char*)inp + ((size_t)(c * 64) * NF + f0) * 4;
        #pragma unroll
        for (int i = tid; i < 2048; i += 512)
            cpa16(sb + SM1_STAGE + buf * 33792 + (i >> 5) * 528 + (i & 31) * 16,
                  xg + (size_t)(i >> 5) * (NF * 4) + (i & 31) * 16);
        const char* wg = (const char*)g_w1p + (size_t)c * 32768;
        #pragma unroll
        for (int i = tid; i < 2048; i += 512)
            cpa16(sb + SM1_W + buf * 36864 + (i >> 3) * 144 + (i & 7) * 16,
                  wg + i * 16);
    };

    load_chunk(0, 0);
    CPA_COMMIT();

    const int fcv = tid & 127, kg = tid >> 7;     // convert-pass assignment

    for (int c = 0; c < 8; c++) {
        const int buf = c & 1;
        CPA_WAIT(0);
        __syncthreads();                           // x(c)+W(c) ready; old bufs free

        if (c < 7) { load_chunk(c + 1, buf ^ 1); CPA_COMMIT(); }

        {   // convert stage -> fp16 plane (each element exactly once)
            const float* st = (const float*)(smem + SM1_STAGE + buf * 33792);
            __half* xh = (__half*)(smem + SM1_XH + buf * 18432);
            #pragma unroll
            for (int kk = 0; kk < 16; kk += 2) {
                int k = kg * 16 + kk;
                float v0 = st[k * 132 + fcv];
                float v1 = st[(k + 1) * 132 + fcv];
                *(uint32_t*)(xh + fcv * 72 + k) =
                    pack_h2(__float2half_rn(v0), __float2half_rn(v1));
            }
        }
        __syncthreads();                           // plane ready

        const __half* xh = (const __half*)(smem + SM1_XH + buf * 18432);
        const __half* ws = (const __half*)(smem + SM1_W + buf * 36864);

        #pragma unroll
        for (int ks = 0; ks < 4; ks++) {
            uint32_t aa[2][4];
            #pragma unroll
            for (int mt = 0; mt < 2; mt++)
                #pragma unroll
                for (int r = 0; r < 4; r++) {
                    int row = fw + mt * 16 + g + ((r & 1) << 3);
                    int kc  = ks * 16 + 2 * t + ((r >> 1) << 3);
                    aa[mt][r] = *(const uint32_t*)(xh + row * 72 + kc);
                }
            uint32_t bb[8][2];
            #pragma unroll
            for (int nt = 0; nt < 8; nt++) {
                const __half* wp = ws + (nw + nt * 8 + g) * 72 + ks * 16 + 2 * t;
                bb[nt][0] = *(const uint32_t*)wp;
                bb[nt][1] = *(const uint32_t*)(wp + 8);
            }
            #pragma unroll
            for (int mt = 0; mt < 2; mt++)
                #pragma unroll
                for (int nt = 0; nt < 8; nt++)
                    mma16816(acc[mt][nt], aa[mt], bb[nt]);
        }
    }

    // Epilogue: sigmoid+gate -> stage (a,b) half2 in smem.
    __syncthreads();
    const float* sB1 = (const float*)(smem + SM1_B1);
    __half2* sAB = (__half2*)smem;                 // [128 f][pitch 132]
    #pragma unroll
    for (int mt = 0; mt < 2; mt++)
        #pragma unroll
        for (int nt = 0; nt < 8; nt++) {
            int fl = fw + mt * 16 + g;
            int nl = nw + nt * 8 + 2 * t;
            int j  = nl >> 1;
            float b0 = sB1[nl], b1 = sB1[nl + 1];
            const float* cc = acc[mt][nt];
            float h0 = sigm(cc[0] + b0), h1 = sigm(cc[1] + b1);
            sAB[fl * 132 + j] = __floats2half2_rn(h0 * h1, 1.f - h0);
            h0 = sigm(cc[2] + b0); h1 = sigm(cc[3] + b1);
            sAB[(fl + 8) * 132 + j] = __floats2half2_rn(h0 * h1, 1.f - h0);
        }
    __syncthreads();

    // Coalesced copy to g_ab
    const float4* s4 = (const float4*)smem;
    float4* g4 = (float4*)(g_ab + (size_t)f0 * 128);
    #pragma unroll
    for (int i = tid; i < 4096; i += 512)
        g4[i] = s4[(i >> 5) * 33 + (i & 31)];

    // Fused chunk composites: 4 chunks x 128 lanes = 512 threads
    {
        const int c = tid >> 7, j = tid & 127;
        float A = 1.f, B = 0.f;
        #pragma unroll 8
        for (int tt = 0; tt < 32; tt++) {
            float2 v = __half22float2(sAB[(c * 32 + tt) * 132 + j]);
            B = fmaf(v.x, B, v.y);
            A *= v.x;
        }
        g_comp[(blockIdx.x * 4 + c) * 128 + j] = make_float2(A, B);
    }
}

// ===========================================================================
// Carry scan: state entering each chunk (exclusive). Shuffle-based 3-level
// scan: 2 chunks/thread -> warp shfl scan -> cross-warp scan -> combine.
// ===========================================================================
__global__ void __launch_bounds__(1024) k_scan_carry()
{
    __shared__ float wA[32], wB[32];
    const int j = blockIdx.x, c = threadIdx.x;
    const int lane = c & 31, wid = c >> 5;

    float2 v0 = g_comp[(2 * c)     * 128 + j];
    float2 v1 = g_comp[(2 * c + 1) * 128 + j];
    float A = v1.x * v0.x;
    float B = fmaf(v1.x, v0.y, v1.y);

    // warp-inclusive scan of composites (compose earlier -> later)
    #pragma unroll
    for (int d = 1; d < 32; d <<= 1) {
        float Ap = __shfl_up_sync(0xffffffffu, A, d);
        float Bp = __shfl_up_sync(0xffffffffu, B, d);
        if (lane >= d) { B = fmaf(A, Bp, B); A *= Ap; }
    }
    if (lane == 31) { wA[wid] = A; wB[wid] = B; }
    __syncthreads();
    if (wid == 0) {
        float a = wA[lane], b = wB[lane];
        #pragma unroll
        for (int d = 1; d < 32; d <<= 1) {
            float ap = __shfl_up_sync(0xffffffffu, a, d);
            float bp = __shfl_up_sync(0xffffffffu, b, d);
            if (lane >= d) { b = fmaf(a, bp, b); a *= ap; }
        }
        wA[lane] = a; wB[lane] = b;
    }
    __syncthreads();

    float PB = (wid == 0) ? 0.f : wB[wid - 1];     // composite of earlier warps
    float eA = __shfl_up_sync(0xffffffffu, A, 1);  // thread-exclusive (within warp)
    float eB = __shfl_up_sync(0xffffffffu, B, 1);
    if (lane == 0) { eA = 1.f; eB = 0.f; }
    float Bex = fmaf(eA, PB, eB);                  // state entering chunk 2c

    g_carry[(2 * c)     * 128 + j] = Bex;
    g_carry[(2 * c + 1) * 128 + j] = fmaf(v0.x, Bex, v0.y);
}

// ===========================================================================
// GEMM2 (fused apply): scan-apply reads g_ab DIRECTLY from global (coalesced)
// while W2 streams in via cp.async; z written as fp16 MMA A-plane in smem.
// out[n 256][f 128] = 1 - sigmoid(W2 z + B2).
// smem: z [128][136] f16 | W2 [256][136] f16 | B2 f32
// ===========================================================================
#define SM2_Z    0
#define SM2_W    34816
#define SM2_B2   104448
#define SM2_SIZE 105472

__global__ void __launch_bounds__(512)
k_gemm2(const float* __restrict__ B2, float* __restrict__ out)
{
    extern __shared__ char smem[];
    const uint32_t sb = smem_u32(smem);
    const int tid = threadIdx.x, lane = tid & 31, wid = tid >> 5;
    const int g = lane >> 2, t = lane & 3;
    const int fw = (wid & 3) * 32, nw = (wid >> 2) * 64;
    const int f0 = blockIdx.x * 128;

    if (tid < 256) ((float*)(smem + SM2_B2))[tid] = B2[tid];

    {   // W2 load overlaps the scan-apply below
        const char* wg = (const char*)g_w2p;
        #pragma unroll
        for (int i = tid; i < 4096; i += 512)
            cpa16(sb + SM2_W + (i >> 4) * 272 + (i & 15) * 16, wg + i * 16);
        CPA_COMMIT();
    }

    // Fused scan-apply from GLOBAL ab: thread (c = tid>>7, j = tid&127)
    {
        const int c = tid >> 7, j = tid & 127;
        const __half2* abp = g_ab + (size_t)(f0 + c * 32) * 128 + j;
        __half* zs = (__half*)(smem + SM2_Z);
        float s = g_carry[(blockIdx.x * 4 + c) * 128 + j];
        zs[(c * 32) * 136 + j] = __float2half_rn(s);
        #pragma unroll
        for (int tt = 0; tt < 31; tt++) {
            float2 v = __half22float2(abp[(size_t)tt * 128]);
            s = fmaf(v.x, s, v.y);
            zs[(c * 32 + tt + 1) * 136 + j] = __float2half_rn(s);
        }
    }
    CPA_WAIT(0);
    __syncthreads();

    const __half* sz = (const __half*)(smem + SM2_Z);
    const __half* sw = (const __half*)(smem + SM2_W);

    float acc[2][8][4];
    #pragma unroll
    for (int a = 0; a < 2; a++)
        #pragma unroll
        for (int b = 0; b < 8; b++)
            #pragma unroll
            for (int q = 0; q < 4; q++) acc[a][b][q] = 0.f;

    #pragma unroll
    for (int ks = 0; ks < 8; ks++) {
        uint32_t aa[2][4];
        #pragma unroll
        for (int mt = 0; mt < 2; mt++)
            #pragma unroll
            for (int r = 0; r < 4; r++) {
                int row = fw + mt * 16 + g + ((r & 1) << 3);
                int kc  = ks * 16 + 2 * t + ((r >> 1) << 3);
                aa[mt][r] = *(const uint32_t*)(sz + row * 136 + kc);
            }
        uint32_t bb[8][2];
        #pragma unroll
        for (int nt = 0; nt < 8; nt++) {
            const __half* wp = sw + (nw + nt * 8 + g) * 136 + ks * 16 + 2 * t;
            bb[nt][0] = *(const uint32_t*)wp;
            bb[nt][1] = *(const uint32_t*)(wp + 8);
        }
        #pragma unroll
        for (int mt = 0; mt < 2; mt++)
            #pragma unroll
            for (int nt = 0; nt < 8; nt++)
                mma16816(acc[mt][nt], aa[mt], bb[nt]);
    }

    const float* sB2 = (const float*)(smem + SM2_B2);
    #pragma unroll
    for (int mt = 0; mt < 2; mt++)
        #pragma unroll
        for (int nt = 0; nt < 8; nt++) {
            int fl = fw + mt * 16 + g;
            int nl = nw + nt * 8 + 2 * t;
            const float* cc = acc[mt][nt];
            float b0 = sB2[nl], b1 = sB2[nl + 1];
            out[(size_t)nl       * NF + f0 + fl]     = 1.f / (1.f + __expf(cc[0] + b0));
            out[(size_t)(nl + 1) * NF + f0 + fl]     = 1.f / (1.f + __expf(cc[1] + b1));
            out[(size_t)nl       * NF + f0 + fl + 8] = 1.f / (1.f + __expf(cc[2] + b0));
            out[(size_t)(nl + 1) * NF + f0 + fl + 8] = 1.f / (1.f + __expf(cc[3] + b1));
        }
}

// ===========================================================================
extern "C" void kernel_launch(void* const* d_in, const int* in_sizes, int n_in,
                              void* d_out, int out_size)
{
    const float* inp = (const float*)d_in[0];   // (512, 65536)
    const float* W1  = (const float*)d_in[1];   // (256, 512)
    const float* B1  = (const float*)d_in[2];   // (256, 1)
    const float* W2  = (const float*)d_in[3];   // (256, 128)
    const float* B2  = (const float*)d_in[4];   // (256, 1)
    float* out = (float*)d_out;                 // (256, 65536)

    cudaFuncSetAttribute(k_gemm1, cudaFuncAttributeMaxDynamicSharedMemorySize, SM1_SIZE);
    cudaFuncSetAttribute(k_gemm2, cudaFuncAttributeMaxDynamicSharedMemorySize, SM2_SIZE);

    k_prep_w1<<<512, 256>>>(W1);
    k_prep_w2<<<128, 256>>>(W2);
    k_gemm1<<<NF / 128, 512, SM1_SIZE>>>(inp, B1);
    k_scan_carry<<<128, 1024>>>();
    k_gemm2<<<NF / 128, 512, SM2_SIZE>>>(B2, out);
}